// round 13
// baseline (speedup 1.0000x reference)
#include <cuda_runtime.h>
#include <cuda_bf16.h>
#include <math.h>
#include <stdint.h>

#define BB 4
#define HD_ 256
#define LD_ 512
#define OD_ 256
#define EE 64
#define NN 4096
#define NLOW 1024
#define EPS_ 1e-5f

__device__ __nv_bfloat16 g_highb[BB*HD_*NN];
__device__ __nv_bfloat16 g_lowb [BB*LD_*NN];
__device__ __nv_bfloat16 g_heb  [BB*128*NN];
__device__ __nv_bfloat16 g_leb  [BB*128*NN];
__device__ __nv_bfloat16 g_qb   [BB*128*NN];
__device__ __nv_bfloat16 g_kb   [BB*128*NN];
__device__ __nv_bfloat16 g_vhpb [BB*OD_*NN];
__device__ __nv_bfloat16 g_vlpb [BB*OD_*NN];
__device__ __nv_bfloat16 g_attnb[(size_t)BB*NN*NN];
__device__ float g_part[BB*32*NN];
__device__ float g_inv [BB*NN];
__device__ __nv_bfloat16 g_Whf_b [128*HD_];
__device__ __nv_bfloat16 g_Wlf_b [128*LD_];
__device__ __nv_bfloat16 g_Wq_b  [128*EE];
__device__ __nv_bfloat16 g_Wk_b  [128*EE];
__device__ __nv_bfloat16 g_Wvhe_b[OD_*HD_];
__device__ __nv_bfloat16 g_Wvle_b[OD_*LD_];
__device__ float g_bh[128], g_bl[128], g_bq[128], g_bk[128];
__device__ float g_ao[OD_], g_bo[OD_], g_bph[OD_], g_bpl[OD_];

__global__ void fold_kernel(const float* __restrict__ W_high,
                            const float* __restrict__ sh, const float* __restrict__ bh,
                            const float* __restrict__ mh, const float* __restrict__ vh,
                            const float* __restrict__ W_low,
                            const float* __restrict__ sl, const float* __restrict__ bl,
                            const float* __restrict__ ml, const float* __restrict__ vl,
                            const float* __restrict__ os_, const float* __restrict__ ob,
                            const float* __restrict__ om, const float* __restrict__ ov,
                            const float* __restrict__ W_out,
                            const float* __restrict__ b_vh, const float* __restrict__ b_vl,
                            const float* __restrict__ W_q, const float* __restrict__ b_q,
                            const float* __restrict__ W_k, const float* __restrict__ b_k)
{
    int i = blockIdx.x * blockDim.x + threadIdx.x;
    if (i < 128*HD_) {
        int o = i / HD_;
        g_Whf_b[i] = (o < EE) ? __float2bfloat16_rn(W_high[i] * sh[o] * rsqrtf(vh[o] + EPS_))
                              : __nv_bfloat16(0.f);
    }
    if (i < 128*LD_) {
        int o = i / LD_;
        g_Wlf_b[i] = (o < EE) ? __float2bfloat16_rn(W_low[i] * sl[o] * rsqrtf(vl[o] + EPS_))
                              : __nv_bfloat16(0.f);
    }
    if (i < 128*EE) {
        int o = i >> 6;
        g_Wq_b[i] = (o < EE) ? __float2bfloat16_rn(W_q[i]) : __nv_bfloat16(0.f);
        g_Wk_b[i] = (o < EE) ? __float2bfloat16_rn(W_k[i]) : __nv_bfloat16(0.f);
    }
    if (i < 128) {
        if (i < EE) {
            float ah = sh[i] * rsqrtf(vh[i] + EPS_); g_bh[i] = bh[i] - mh[i] * ah;
            float al = sl[i] * rsqrtf(vl[i] + EPS_); g_bl[i] = bl[i] - ml[i] * al;
            g_bq[i] = b_q[i]; g_bk[i] = b_k[i];
        } else { g_bh[i] = 0.f; g_bl[i] = 0.f; g_bq[i] = 0.f; g_bk[i] = 0.f; }
    }
    if (i < OD_) {
        float a = os_[i] * rsqrtf(ov[i] + EPS_);
        g_ao[i] = a; g_bo[i] = ob[i] - om[i] * a;
    }
    if (i < 2*OD_) {
        int o = (i < OD_) ? i : i - OD_;
        const float* wrow = W_out + (long)o * (2*OD_) + ((i < OD_) ? 0 : OD_);
        const float* bv   = (i < OD_) ? b_vh : b_vl;
        float s = 0.f;
        for (int j = 0; j < OD_; j++) s += wrow[j] * bv[j];
        if (i < OD_) g_bph[o] = s; else g_bpl[o] = s;
    }
}

__global__ void tobf16_kernel(const float* __restrict__ in, __nv_bfloat16* __restrict__ out, long n4)
{
    long i = blockIdx.x * (long)blockDim.x + threadIdx.x;
    if (i >= n4) return;
    float4 v = ((const float4*)in)[i];
    __nv_bfloat162* o = (__nv_bfloat162*)(out + i * 4);
    o[0] = __floats2bfloat162_rn(v.x, v.y);
    o[1] = __floats2bfloat162_rn(v.z, v.w);
}

__global__ void upsample_kernel(const float* __restrict__ low, __nv_bfloat16* __restrict__ out)
{
    int idx = blockIdx.x * blockDim.x + threadIdx.x;
    if (idx >= BB*LD_*NN) return;
    int x = idx & 63, y = (idx >> 6) & 63;
    int bc = idx >> 12;
    float fy = y * 0.5f - 0.25f, fx = x * 0.5f - 0.25f;
    int y0 = (int)floorf(fy); float wy = fy - (float)y0;
    int x0 = (int)floorf(fx); float wx = fx - (float)x0;
    int y1 = min(y0 + 1, 31); y0 = max(y0, 0);
    int x1 = min(x0 + 1, 31); x0 = max(x0, 0);
    const float* src = low + (long)bc * NLOW;
    float v00 = src[y0*32+x0], v01 = src[y0*32+x1];
    float v10 = src[y1*32+x0], v11 = src[y1*32+x1];
    out[idx] = __float2bfloat16_rn((1.f-wy)*((1.f-wx)*v00 + wx*v01) + wy*((1.f-wx)*v10 + wx*v11));
}

enum { E_NONE = 0, E_BIAS = 1, E_BIAS_RELU = 2, E_EXP = 4 };

__global__ __launch_bounds__(256)
void gemm_small(const float* __restrict__ A, const float* __restrict__ B,
                __nv_bfloat16* __restrict__ C, int K, int lda, int ldb, int ldc)
{
    __shared__ float As[16][68];
    __shared__ float Bs[16][68];
    int m0 = blockIdx.y * 64, n0 = blockIdx.x * 64;
    int tid = threadIdx.x;
    int row = tid >> 4, col = tid & 15;
    float acc[4][4] = {};
    for (int k0 = 0; k0 < K; k0 += 16) {
        {
            int kk = tid & 15, ms = tid >> 4;
            #pragma unroll
            for (int r = 0; r < 4; r++) As[kk][ms + 16*r] = A[(long)(m0 + ms + 16*r) * lda + (k0 + kk)];
        }
        {
            int n = tid & 63, ks = tid >> 6;
            #pragma unroll
            for (int r = 0; r < 4; r++) Bs[ks*4+r][n] = B[(long)(k0 + ks*4 + r) * ldb + (n0 + n)];
        }
        __syncthreads();
        #pragma unroll
        for (int kk = 0; kk < 16; kk++) {
            float a0 = As[kk][row*4+0], a1 = As[kk][row*4+1];
            float a2 = As[kk][row*4+2], a3 = As[kk][row*4+3];
            float b0 = Bs[kk][col*4+0], b1 = Bs[kk][col*4+1];
            float b2 = Bs[kk][col*4+2], b3 = Bs[kk][col*4+3];
            acc[0][0] += a0*b0; acc[0][1] += a0*b1; acc[0][2] += a0*b2; acc[0][3] += a0*b3;
            acc[1][0] += a1*b0; acc[1][1] += a1*b1; acc[1][2] += a1*b2; acc[1][3] += a1*b3;
            acc[2][0] += a2*b0; acc[2][1] += a2*b1; acc[2][2] += a2*b2; acc[2][3] += a2*b3;
            acc[3][0] += a3*b0; acc[3][1] += a3*b1; acc[3][2] += a3*b2; acc[3][3] += a3*b3;
        }
        __syncthreads();
    }
    #pragma unroll
    for (int i = 0; i < 4; i++)
        #pragma unroll
        for (int j = 0; j < 4; j++)
            C[(long)(m0 + row*4 + i) * ldc + n0 + col*4 + j] = __float2bfloat16_rn(acc[i][j]);
}

__device__ __forceinline__ uint32_t smaddr(const void* p) {
    return (uint32_t)__cvta_generic_to_shared(p);
}
__device__ __forceinline__ void cpasync16(uint32_t dst, const void* src) {
    asm volatile("cp.async.cg.shared.global [%0],[%1],16;" :: "r"(dst), "l"(src));
}
__device__ __forceinline__ void ldsm4(uint32_t& r0, uint32_t& r1, uint32_t& r2, uint32_t& r3, uint32_t a) {
    asm volatile("ldmatrix.sync.aligned.m8n8.x4.shared.b16 {%0,%1,%2,%3},[%4];"
                 : "=r"(r0), "=r"(r1), "=r"(r2), "=r"(r3) : "r"(a));
}
__device__ __forceinline__ void ldsm4t(uint32_t& r0, uint32_t& r1, uint32_t& r2, uint32_t& r3, uint32_t a) {
    asm volatile("ldmatrix.sync.aligned.m8n8.x4.trans.shared.b16 {%0,%1,%2,%3},[%4];"
                 : "=r"(r0), "=r"(r1), "=r"(r2), "=r"(r3) : "r"(a));
}
__device__ __forceinline__ void mma16816(float* d, const uint32_t* a, const uint32_t* b) {
    asm volatile("mma.sync.aligned.m16n8k16.row.col.f32.bf16.bf16.f32 "
                 "{%0,%1,%2,%3},{%4,%5,%6,%7},{%8,%9},{%0,%1,%2,%3};"
                 : "+f"(d[0]), "+f"(d[1]), "+f"(d[2]), "+f"(d[3])
                 : "r"(a[0]), "r"(a[1]), "r"(a[2]), "r"(a[3]), "r"(b[0]), "r"(b[1]));
}

// ---- R8 mma.sync GEMM: 128x128x32 tile, 8 warps (2x4), warp tile 64x32 -----
template<int TA, int TB, int EPI, int OB>
__global__ __launch_bounds__(256)
void mma_gemm(const __nv_bfloat16* __restrict__ A, const __nv_bfloat16* __restrict__ B,
              void* __restrict__ Cv, int K, int lda, int ldb, int ldc,
              long sA, long sB, long sC,
              const float* __restrict__ bias, float* __restrict__ partial)
{
    constexpr int ASZ = TA ? 32*136 : 128*40;
    constexpr int BSZ = TB ? 128*40 : 32*136;
    __shared__ __align__(16) __nv_bfloat16 Ash[3][ASZ];
    __shared__ __align__(16) __nv_bfloat16 Bsh[3][BSZ];
    __shared__ float rsb[(EPI == E_EXP) ? 128 : 1][4];

    int b = blockIdx.z;
    A += (long)b * sA; B += (long)b * sB;
    float* Cf = (float*)Cv + (long)b * sC;
    __nv_bfloat16* Cb = (__nv_bfloat16*)Cv + (long)b * sC;

    int n0 = blockIdx.x * 128, m0 = blockIdx.y * 128;
    int tid = threadIdx.x;
    int wid = tid >> 5, lane = tid & 31;
    int wm = (wid >> 2) * 64, wn = (wid & 3) * 32;
    float acc[4][4][4] = {};
    int KT = K / 32;

    auto issueA = [&](int kt, int buf) {
        int k0 = kt * 32;
        if (TA) {
            #pragma unroll
            for (int it = 0; it < 2; it++) {
                int kr = (tid >> 4) + it * 16, mc = (tid & 15) * 8;
                cpasync16(smaddr(&Ash[buf][kr * 136 + mc]), A + (long)(k0 + kr) * lda + m0 + mc);
            }
        } else {
            #pragma unroll
            for (int it = 0; it < 2; it++) {
                int mr = (tid >> 2) + it * 64, kc = (tid & 3) * 8;
                cpasync16(smaddr(&Ash[buf][mr * 40 + kc]), A + (long)(m0 + mr) * lda + k0 + kc);
            }
        }
    };
    auto issueB = [&](int kt, int buf) {
        int k0 = kt * 32;
        if (TB) {
            #pragma unroll
            for (int it = 0; it < 2; it++) {
                int nr = (tid >> 2) + it * 64, kc = (tid & 3) * 8;
                cpasync16(smaddr(&Bsh[buf][nr * 40 + kc]), B + (long)(n0 + nr) * ldb + k0 + kc);
            }
        } else {
            #pragma unroll
            for (int it = 0; it < 2; it++) {
                int kr = (tid >> 4) + it * 16, nc = (tid & 15) * 8;
                cpasync16(smaddr(&Bsh[buf][kr * 136 + nc]), B + (long)(k0 + kr) * ldb + n0 + nc);
            }
        }
    };

    issueA(0, 0); issueB(0, 0);
    asm volatile("cp.async.commit_group;");
    if (KT > 1) { issueA(1, 1); issueB(1, 1); asm volatile("cp.async.commit_group;"); }

    for (int kt = 0; kt < KT; kt++) {
        if (kt < KT - 1) asm volatile("cp.async.wait_group 1;");
        else             asm volatile("cp.async.wait_group 0;");
        __syncthreads();
        if (kt + 2 < KT) {
            issueA(kt + 2, (kt + 2) % 3);
            issueB(kt + 2, (kt + 2) % 3);
            asm volatile("cp.async.commit_group;");
        }
        int cur = kt % 3;
        #pragma unroll
        for (int ks = 0; ks < 2; ks++) {
            uint32_t af[4][4];
            #pragma unroll
            for (int mf = 0; mf < 4; mf++) {
                if (!TA) {
                    uint32_t a = smaddr(&Ash[cur][(wm + mf*16 + (lane & 15)) * 40 + ks*16 + (lane >> 4) * 8]);
                    ldsm4(af[mf][0], af[mf][1], af[mf][2], af[mf][3], a);
                } else {
                    uint32_t a = smaddr(&Ash[cur][(ks*16 + (lane >> 4) * 8 + (lane & 7)) * 136
                                                  + wm + mf*16 + ((lane >> 3) & 1) * 8]);
                    ldsm4t(af[mf][0], af[mf][1], af[mf][2], af[mf][3], a);
                }
            }
            uint32_t bfr[4][2];
            #pragma unroll
            for (int nf2 = 0; nf2 < 2; nf2++) {
                uint32_t r0, r1, r2, r3;
                if (TB) {
                    uint32_t a = smaddr(&Bsh[cur][(wn + nf2*16 + (lane & 7) + (lane >> 4) * 8) * 40
                                                  + ks*16 + ((lane >> 3) & 1) * 8]);
                    ldsm4(r0, r1, r2, r3, a);
                } else {
                    uint32_t a = smaddr(&Bsh[cur][(ks*16 + ((lane >> 3) & 1) * 8 + (lane & 7)) * 136
                                                  + wn + nf2*16 + (lane >> 4) * 8]);
                    ldsm4t(r0, r1, r2, r3, a);
                }
                bfr[nf2*2][0] = r0; bfr[nf2*2][1] = r1;
                bfr[nf2*2+1][0] = r2; bfr[nf2*2+1][1] = r3;
            }
            #pragma unroll
            for (int mf = 0; mf < 4; mf++)
                #pragma unroll
                for (int nf = 0; nf < 4; nf++)
                    mma16816(acc[mf][nf], af[mf], bfr[nf]);
        }
        __syncthreads();
    }

    if (EPI == E_EXP) {
        float rsum[4][2] = {};
        #pragma unroll
        for (int mf = 0; mf < 4; mf++)
            #pragma unroll
            for (int nf = 0; nf < 4; nf++)
                #pragma unroll
                for (int h = 0; h < 2; h++) {
                    int r = m0 + wm + mf*16 + (lane >> 2) + h*8;
                    int c = n0 + wn + nf*8 + (lane & 3) * 2;
                    float e0 = __expf(fminf(acc[mf][nf][h*2],   50.f));
                    float e1 = __expf(fminf(acc[mf][nf][h*2+1], 50.f));
                    *(__nv_bfloat162*)(Cb + (long)r * ldc + c) = __floats2bfloat162_rn(e0, e1);
                    rsum[mf][h] += e0 + e1;
                }
        #pragma unroll
        for (int mf = 0; mf < 4; mf++)
            #pragma unroll
            for (int h = 0; h < 2; h++) {
                rsum[mf][h] += __shfl_xor_sync(0xffffffffu, rsum[mf][h], 1);
                rsum[mf][h] += __shfl_xor_sync(0xffffffffu, rsum[mf][h], 2);
                if ((lane & 3) == 0)
                    rsb[wm + mf*16 + (lane >> 2) + h*8][wid & 3] = rsum[mf][h];
            }
        __syncthreads();
        if (tid < 128)
            partial[((long)b*32 + blockIdx.x)*NN + (m0 + tid)] =
                rsb[tid][0] + rsb[tid][1] + rsb[tid][2] + rsb[tid][3];
        return;
    }

    #pragma unroll
    for (int mf = 0; mf < 4; mf++) {
        #pragma unroll
        for (int nf = 0; nf < 4; nf++) {
            int rbase = m0 + wm + mf*16 + (lane >> 2);
            int c = n0 + wn + nf*8 + (lane & 3) * 2;
            #pragma unroll
            for (int h = 0; h < 2; h++) {
                int r = rbase + h * 8;
                long off = (long)r * ldc + c;
                float v0 = acc[mf][nf][h*2], v1 = acc[mf][nf][h*2+1];
                if (EPI == E_BIAS) {
                    float bv = bias[r]; v0 += bv; v1 += bv;
                } else if (EPI == E_BIAS_RELU) {
                    float bv = bias[r];
                    v0 = fmaxf(v0 + bv, 0.f); v1 = fmaxf(v1 + bv, 0.f);
                }
                if (OB) *(__nv_bfloat162*)(Cb + off) = __floats2bfloat162_rn(v0, v1);
                else    { Cf[off] = v0; Cf[off+1] = v1; }
            }
        }
    }
}

// ---- fused attention-output kernel: dual accumulators, no z round-trip -----
// out[c,n] = high[c,n] + gamma * relu(ao[c]*(inv[n]*Sum_m vh[c,m]E[n,m]
//                                           + Sum_m vls[c,m]E[m,n]) + bo[c])
#define FA_ASZ (128*40)
#define FA_B2SZ (32*136)
#define FA_SMEM ((3*(FA_ASZ*3 + FA_B2SZ)) * 2)

__global__ __launch_bounds__(256)
void attn_out_kernel(const __nv_bfloat16* __restrict__ VH, const __nv_bfloat16* __restrict__ VLS,
                     const __nv_bfloat16* __restrict__ E, const float* __restrict__ inv,
                     const float* __restrict__ resid, const float* __restrict__ ao,
                     const float* __restrict__ bo, const float* __restrict__ gammap,
                     float* __restrict__ out)
{
    extern __shared__ __align__(16) __nv_bfloat16 smp[];
    int b = blockIdx.z;
    const __nv_bfloat16* Avh = VH  + (long)b * OD_ * NN;
    const __nv_bfloat16* Avl = VLS + (long)b * OD_ * NN;
    const __nv_bfloat16* Eg  = E + (long)b * NN * NN;
    const float* invB = inv + (long)b * NN;
    const float* resB = resid + (long)b * OD_ * NN;
    float* outB = out + (long)b * OD_ * NN;

    int n0 = blockIdx.x * 128, m0 = blockIdx.y * 128;
    int tid = threadIdx.x;
    int wid = tid >> 5, lane = tid & 31;
    int wm = (wid >> 2) * 64, wn = (wid & 3) * 32;
    float acc1[4][4][4] = {}, acc2[4][4][4] = {};
    const int KT = NN / 32;

    // smem layout: A1[3] | A2[3] | B1[3] (TB=1, 128x40) | B2[3] (TB=0, 32x136)
    auto A1s = [&](int buf) { return smp + buf * FA_ASZ; };
    auto A2s = [&](int buf) { return smp + (3 + buf) * FA_ASZ; };
    auto B1s = [&](int buf) { return smp + (6 + buf) * FA_ASZ; };
    auto B2s = [&](int buf) { return smp + 9 * FA_ASZ + buf * FA_B2SZ; };

    auto issue = [&](int kt, int buf) {
        int k0 = kt * 32;
        #pragma unroll
        for (int it = 0; it < 2; it++) {
            int mr = (tid >> 2) + it * 64, kc = (tid & 3) * 8;
            cpasync16(smaddr(A1s(buf) + mr * 40 + kc), Avh + (long)(m0 + mr) * NN + k0 + kc);
            cpasync16(smaddr(A2s(buf) + mr * 40 + kc), Avl + (long)(m0 + mr) * NN + k0 + kc);
            cpasync16(smaddr(B1s(buf) + mr * 40 + kc), Eg + (long)(n0 + mr) * NN + k0 + kc);
        }
        #pragma unroll
        for (int it = 0; it < 2; it++) {
            int kr = (tid >> 4) + it * 16, nc = (tid & 15) * 8;
            cpasync16(smaddr(B2s(buf) + kr * 136 + nc), Eg + (long)(k0 + kr) * NN + n0 + nc);
        }
    };

    issue(0, 0);
    asm volatile("cp.async.commit_group;");
    issue(1, 1);
    asm volatile("cp.async.commit_group;");

    for (int kt = 0; kt < KT; kt++) {
        if (kt < KT - 1) asm volatile("cp.async.wait_group 1;");
        else             asm volatile("cp.async.wait_group 0;");
        __syncthreads();
        if (kt + 2 < KT) { issue(kt + 2, (kt + 2) % 3); asm volatile("cp.async.commit_group;"); }
        int cur = kt % 3;
        #pragma unroll
        for (int ks = 0; ks < 2; ks++) {
            uint32_t a1f[4][4], a2f[4][4];
            #pragma unroll
            for (int mf = 0; mf < 4; mf++) {
                uint32_t off = (wm + mf*16 + (lane & 15)) * 40 + ks*16 + (lane >> 4) * 8;
                ldsm4(a1f[mf][0], a1f[mf][1], a1f[mf][2], a1f[mf][3], smaddr(A1s(cur) + off));
                ldsm4(a2f[mf][0], a2f[mf][1], a2f[mf][2], a2f[mf][3], smaddr(A2s(cur) + off));
            }
            uint32_t b1f[4][2], b2f[4][2];
            #pragma unroll
            for (int nf2 = 0; nf2 < 2; nf2++) {
                uint32_t r0, r1, r2, r3;
                // B1: TB=1 layout (E row n, contiguous k)
                ldsm4(r0, r1, r2, r3, smaddr(B1s(cur)
                    + (wn + nf2*16 + (lane & 7) + (lane >> 4) * 8) * 40 + ks*16 + ((lane >> 3) & 1) * 8));
                b1f[nf2*2][0] = r0; b1f[nf2*2][1] = r1;
                b1f[nf2*2+1][0] = r2; b1f[nf2*2+1][1] = r3;
                // B2: TB=0 layout (E row k, contiguous n)
                ldsm4t(r0, r1, r2, r3, smaddr(B2s(cur)
                    + (ks*16 + ((lane >> 3) & 1) * 8 + (lane & 7)) * 136 + wn + nf2*16 + (lane >> 4) * 8));
                b2f[nf2*2][0] = r0; b2f[nf2*2][1] = r1;
                b2f[nf2*2+1][0] = r2; b2f[nf2*2+1][1] = r3;
            }
            #pragma unroll
            for (int mf = 0; mf < 4; mf++)
                #pragma unroll
                for (int nf = 0; nf < 4; nf++) {
                    mma16816(acc1[mf][nf], a1f[mf], b1f[nf]);
                    mma16816(acc2[mf][nf], a2f[mf], b2f[nf]);
                }
        }
        __syncthreads();
    }

    float gam = gammap[0];
    #pragma unroll
    for (int mf = 0; mf < 4; mf++) {
        #pragma unroll
        for (int nf = 0; nf < 4; nf++) {
            int rbase = m0 + wm + mf*16 + (lane >> 2);
            int c = n0 + wn + nf*8 + (lane & 3) * 2;
            float i0 = invB[c], i1 = invB[c+1];
            #pragma unroll
            for (int h = 0; h < 2; h++) {
                int r = rbase + h * 8;
                long off = (long)r * NN + c;
                float sc = ao[r], sf = bo[r];
                float v0 = acc1[mf][nf][h*2]   * i0 + acc2[mf][nf][h*2];
                float v1 = acc1[mf][nf][h*2+1] * i1 + acc2[mf][nf][h*2+1];
                v0 = fmaxf(v0 * sc + sf, 0.f);
                v1 = fmaxf(v1 * sc + sf, 0.f);
                outB[off]   = resB[off]   + gam * v0;
                outB[off+1] = resB[off+1] + gam * v1;
            }
        }
    }
}

__global__ void inv_kernel(const float* __restrict__ part, float* __restrict__ inv)
{
    int i = blockIdx.x * 256 + threadIdx.x;
    int b = i >> 12, n = i & (NN - 1);
    float s = 0.f;
    #pragma unroll 8
    for (int x = 0; x < 32; x++) s += part[((long)b*32 + x)*NN + n];
    inv[i] = 1.f / s;
}

__global__ void scale_vl_kernel(__nv_bfloat16* __restrict__ vl, const float* __restrict__ inv)
{
    long i = blockIdx.x * 256L + threadIdx.x;
    int n = (int)(i & 2047) * 2;
    long b = i >> 19;
    const float* ib = inv + b * NN;
    __nv_bfloat162 v = ((__nv_bfloat162*)vl)[i];
    float2 f = __bfloat1622float2(v);
    ((__nv_bfloat162*)vl)[i] = __floats2bfloat162_rn(f.x * ib[n], f.y * ib[n+1]);
}

#define SYM(p, T, s) do { void* t_; cudaGetSymbolAddress(&t_, s); p = (T*)t_; } while (0)

extern "C" void kernel_launch(void* const* d_in, const int* in_sizes, int n_in,
                              void* d_out, int out_size)
{
    const float* high   = (const float*)d_in[0];
    const float* lowf   = (const float*)d_in[1];
    const float* W_high = (const float*)d_in[2];
    const float* bn_hs  = (const float*)d_in[3];
    const float* bn_hb  = (const float*)d_in[4];
    const float* bn_hm  = (const float*)d_in[5];
    const float* bn_hv  = (const float*)d_in[6];
    const float* W_low  = (const float*)d_in[7];
    const float* bn_ls  = (const float*)d_in[8];
    const float* bn_lb  = (const float*)d_in[9];
    const float* bn_lm  = (const float*)d_in[10];
    const float* bn_lv  = (const float*)d_in[11];
    const float* W_q    = (const float*)d_in[12];
    const float* b_q    = (const float*)d_in[13];
    const float* W_k    = (const float*)d_in[14];
    const float* b_k    = (const float*)d_in[15];
    const float* W_vh   = (const float*)d_in[16];
    const float* b_vh   = (const float*)d_in[17];
    const float* W_vl   = (const float*)d_in[18];
    const float* b_vl   = (const float*)d_in[19];
    const float* W_out  = (const float*)d_in[20];
    const float* bn_os  = (const float*)d_in[21];
    const float* bn_ob  = (const float*)d_in[22];
    const float* bn_om  = (const float*)d_in[23];
    const float* bn_ov  = (const float*)d_in[24];
    const float* gamma  = (const float*)d_in[25];
    float* out = (float*)d_out;

    __nv_bfloat16 *pHighb, *pLowb, *pHeb, *pLeb, *pQb, *pKb, *pVhpb, *pVlpb, *pAttnb;
    __nv_bfloat16 *pWhf, *pWlf, *pWq, *pWk, *pWvhe, *pWvle;
    float *pPart, *pInv, *pBh, *pBl, *pBq, *pBk, *pAo, *pBo, *pBph, *pBpl;
    SYM(pHighb, __nv_bfloat16, g_highb); SYM(pLowb, __nv_bfloat16, g_lowb);
    SYM(pHeb, __nv_bfloat16, g_heb); SYM(pLeb, __nv_bfloat16, g_leb);
    SYM(pQb, __nv_bfloat16, g_qb); SYM(pKb, __nv_bfloat16, g_kb);
    SYM(pVhpb, __nv_bfloat16, g_vhpb); SYM(pVlpb, __nv_bfloat16, g_vlpb);
    SYM(pAttnb, __nv_bfloat16, g_attnb);
    SYM(pWhf, __nv_bfloat16, g_Whf_b); SYM(pWlf, __nv_bfloat16, g_Wlf_b);
    SYM(pWq, __nv_bfloat16, g_Wq_b); SYM(pWk, __nv_bfloat16, g_Wk_b);
    SYM(pWvhe, __nv_bfloat16, g_Wvhe_b); SYM(pWvle, __nv_bfloat16, g_Wvle_b);
    SYM(pPart, float, g_part); SYM(pInv, float, g_inv);
    SYM(pBh, float, g_bh); SYM(pBl, float, g_bl); SYM(pBq, float, g_bq); SYM(pBk, float, g_bk);
    SYM(pAo, float, g_ao); SYM(pBo, float, g_bo); SYM(pBph, float, g_bph); SYM(pBpl, float, g_bpl);

    cudaFuncSetAttribute(attn_out_kernel, cudaFuncAttributeMaxDynamicSharedMemorySize, FA_SMEM);

    fold_kernel<<<256, 256>>>(W_high, bn_hs, bn_hb, bn_hm, bn_hv,
                              W_low, bn_ls, bn_lb, bn_lm, bn_lv,
                              bn_os, bn_ob, bn_om, bn_ov,
                              W_out, b_vh, b_vl, W_q, b_q, W_k, b_k);
    gemm_small<<<dim3(4,4,1), 256>>>(W_out, W_vh, pWvhe, 256, 512, 256, 256);
    gemm_small<<<dim3(8,4,1), 256>>>(W_out + 256, W_vl, pWvle, 256, 512, 512, 512);
    tobf16_kernel<<<(BB*HD_*NN/4 + 255)/256, 256>>>(high, pHighb, (long)BB*HD_*NN/4);
    upsample_kernel<<<(BB*LD_*NN + 255)/256, 256>>>(lowf, pLowb);

    mma_gemm<0,0,E_BIAS_RELU,1><<<dim3(32,1,BB), 256>>>(pWhf, pHighb, pHeb,
        HD_, HD_, NN, NN, 0, (long)HD_*NN, (long)128*NN, pBh, nullptr);
    mma_gemm<0,0,E_BIAS_RELU,1><<<dim3(32,1,BB), 256>>>(pWlf, pLowb, pLeb,
        LD_, LD_, NN, NN, 0, (long)LD_*NN, (long)128*NN, pBl, nullptr);
    mma_gemm<0,0,E_BIAS,1><<<dim3(32,1,BB), 256>>>(pWq, pHeb, pQb,
        EE, EE, NN, NN, 0, (long)128*NN, (long)128*NN, pBq, nullptr);
    mma_gemm<0,0,E_BIAS,1><<<dim3(32,1,BB), 256>>>(pWk, pLeb, pKb,
        EE, EE, NN, NN, 0, (long)128*NN, (long)128*NN, pBk, nullptr);
    mma_gemm<0,0,E_BIAS,1><<<dim3(32,2,BB), 256>>>(pWvhe, pHighb, pVhpb,
        HD_, HD_, NN, NN, 0, (long)HD_*NN, (long)OD_*NN, pBph, nullptr);
    mma_gemm<0,0,E_BIAS,1><<<dim3(32,2,BB), 256>>>(pWvle, pLowb, pVlpb,
        LD_, LD_, NN, NN, 0, (long)LD_*NN, (long)OD_*NN, pBpl, nullptr);

    // energy -> exp(logit) + partial row sums
    mma_gemm<1,0,E_EXP,1><<<dim3(32,32,BB), 256>>>(pQb, pKb, pAttnb,
        EE, NN, NN, NN, (long)128*NN, (long)128*NN, (long)NN*NN, nullptr, pPart);
    inv_kernel<<<BB*NN/256, 256>>>(pPart, pInv);
    scale_vl_kernel<<<(int)((long)BB*OD_*NN/2/256), 256>>>(pVlpb, pInv);

    // fused steps 9+10: out = high + gamma*relu(ao*(vh@E^T*inv + vls@E) + bo)
    attn_out_kernel<<<dim3(32,2,BB), 256, FA_SMEM>>>(pVhpb, pVlpb, pAttnb, pInv,
                                                     high, pAo, pBo, gamma, out);
}

// round 14
// speedup vs baseline: 1.0875x; 1.0875x over previous
#include <cuda_runtime.h>
#include <cuda_bf16.h>
#include <math.h>
#include <stdint.h>

#define BB 4
#define HD_ 256
#define LD_ 512
#define OD_ 256
#define EE 64
#define NN 4096
#define NLOW 1024
#define EPS_ 1e-5f

__device__ __nv_bfloat16 g_highb[BB*HD_*NN];
__device__ __nv_bfloat16 g_lowb [BB*LD_*NN];
__device__ __nv_bfloat16 g_heb  [BB*128*NN];
__device__ __nv_bfloat16 g_leb  [BB*128*NN];
__device__ __nv_bfloat16 g_kb   [BB*128*NN];
__device__ __nv_bfloat16 g_vhpb [BB*OD_*NN];
__device__ __nv_bfloat16 g_vlpb [BB*OD_*NN];
__device__ float g_z   [BB*OD_*NN];
__device__ __nv_bfloat16 g_attnb[(size_t)BB*NN*NN];
__device__ float g_part[BB*32*NN];
__device__ float g_inv [BB*NN];
__device__ float g_w   [BB*NN];
// stacked folded weights: rows 0-127 = proj (pad>=64 zero), rows 128-383 = value
__device__ __nv_bfloat16 g_Wsh[384*HD_];
__device__ __nv_bfloat16 g_Wsl[384*LD_];
__device__ __nv_bfloat16 g_Wm [128*EE];     // WqT*Wk, padded rows
__device__ float g_bsh[384], g_bsl[384];
__device__ float g_wv[EE];
__device__ float g_c;
__device__ float g_ao[OD_], g_bo[OD_];

__global__ void fold_kernel(const float* __restrict__ W_high,
                            const float* __restrict__ sh, const float* __restrict__ bh,
                            const float* __restrict__ mh, const float* __restrict__ vh,
                            const float* __restrict__ W_low,
                            const float* __restrict__ sl, const float* __restrict__ bl,
                            const float* __restrict__ ml, const float* __restrict__ vl,
                            const float* __restrict__ os_, const float* __restrict__ ob,
                            const float* __restrict__ om, const float* __restrict__ ov,
                            const float* __restrict__ W_out,
                            const float* __restrict__ b_vh, const float* __restrict__ b_vl,
                            const float* __restrict__ W_q, const float* __restrict__ b_q,
                            const float* __restrict__ W_k, const float* __restrict__ b_k)
{
    int i = blockIdx.x * blockDim.x + threadIdx.x;
    if (i < 128*HD_) {
        int o = i / HD_;
        g_Wsh[i] = (o < EE) ? __float2bfloat16_rn(W_high[i] * sh[o] * rsqrtf(vh[o] + EPS_))
                            : __nv_bfloat16(0.f);
    }
    if (i < 128*LD_) {
        int o = i / LD_;
        g_Wsl[i] = (o < EE) ? __float2bfloat16_rn(W_low[i] * sl[o] * rsqrtf(vl[o] + EPS_))
                            : __nv_bfloat16(0.f);
    }
    if (i < 128*EE) {   // M[e,f] = sum_o Wq[o,e]*Wk[o,f]
        int e = i >> 6, f = i & 63;
        if (e < EE) {
            float s = 0.f;
            for (int o = 0; o < EE; o++) s += W_q[o*EE + e] * W_k[o*EE + f];
            g_Wm[i] = __float2bfloat16_rn(s);
        } else g_Wm[i] = __nv_bfloat16(0.f);
    }
    if (i < EE) {       // wv[f] = sum_o bq[o]*Wk[o,f]
        float s = 0.f;
        for (int o = 0; o < EE; o++) s += b_q[o] * W_k[o*EE + i];
        g_wv[i] = s;
        if (i == 0) {
            float c = 0.f;
            for (int o = 0; o < EE; o++) c += b_q[o] * b_k[o];
            g_c = c;
        }
    }
    if (i < 128) {
        if (i < EE) {
            float ah = sh[i] * rsqrtf(vh[i] + EPS_); g_bsh[i] = bh[i] - mh[i] * ah;
            float al = sl[i] * rsqrtf(vl[i] + EPS_); g_bsl[i] = bl[i] - ml[i] * al;
        } else { g_bsh[i] = 0.f; g_bsl[i] = 0.f; }
    }
    if (i < OD_) {
        float a = os_[i] * rsqrtf(ov[i] + EPS_);
        g_ao[i] = a; g_bo[i] = ob[i] - om[i] * a;
    }
    if (i < 2*OD_) {    // combined value biases into stacked bias rows 128-383
        int o = (i < OD_) ? i : i - OD_;
        const float* wrow = W_out + (long)o * (2*OD_) + ((i < OD_) ? 0 : OD_);
        const float* bv   = (i < OD_) ? b_vh : b_vl;
        float s = 0.f;
        for (int j = 0; j < OD_; j++) s += wrow[j] * bv[j];
        if (i < OD_) g_bsh[128 + o] = s; else g_bsl[128 + o] = s;
    }
}

__global__ void tobf16_kernel(const float* __restrict__ in, __nv_bfloat16* __restrict__ out, long n4)
{
    long i = blockIdx.x * (long)blockDim.x + threadIdx.x;
    if (i >= n4) return;
    float4 v = ((const float4*)in)[i];
    __nv_bfloat162* o = (__nv_bfloat162*)(out + i * 4);
    o[0] = __floats2bfloat162_rn(v.x, v.y);
    o[1] = __floats2bfloat162_rn(v.z, v.w);
}

__global__ void upsample_kernel(const float* __restrict__ low, __nv_bfloat16* __restrict__ out)
{
    int idx = blockIdx.x * blockDim.x + threadIdx.x;
    if (idx >= BB*LD_*NN) return;
    int x = idx & 63, y = (idx >> 6) & 63;
    int bc = idx >> 12;
    float fy = y * 0.5f - 0.25f, fx = x * 0.5f - 0.25f;
    int y0 = (int)floorf(fy); float wy = fy - (float)y0;
    int x0 = (int)floorf(fx); float wx = fx - (float)x0;
    int y1 = min(y0 + 1, 31); y0 = max(y0, 0);
    int x1 = min(x0 + 1, 31); x0 = max(x0, 0);
    const float* src = low + (long)bc * NLOW;
    float v00 = src[y0*32+x0], v01 = src[y0*32+x1];
    float v10 = src[y1*32+x0], v11 = src[y1*32+x1];
    out[idx] = __float2bfloat16_rn((1.f-wy)*((1.f-wx)*v00 + wx*v01) + wy*((1.f-wx)*v10 + wx*v11));
}

// w[b,m] = exp(sum_f wv[f]*le[b,f,m] + c)
__global__ void wcol_kernel(const __nv_bfloat16* __restrict__ le, float* __restrict__ w)
{
    int i = blockIdx.x * 256 + threadIdx.x;     // BB*NN
    int b = i >> 12, m = i & (NN - 1);
    const __nv_bfloat16* lb = le + (long)b * 128 * NN + m;
    float s = g_c;
    #pragma unroll 8
    for (int f = 0; f < EE; f++) s += g_wv[f] * __bfloat162float(lb[(long)f * NN]);
    w[i] = __expf(s);
}

enum { E_NONE = 0, E_STACK = 1, E_EXP = 4, E_INV = 5, E_FINAL = 6 };

__global__ __launch_bounds__(256)
void gemm_small(const float* __restrict__ A, const float* __restrict__ B,
                __nv_bfloat16* __restrict__ C, int K, int lda, int ldb, int ldc)
{
    __shared__ float As[16][68];
    __shared__ float Bs[16][68];
    int m0 = blockIdx.y * 64, n0 = blockIdx.x * 64;
    int tid = threadIdx.x;
    int row = tid >> 4, col = tid & 15;
    float acc[4][4] = {};
    for (int k0 = 0; k0 < K; k0 += 16) {
        {
            int kk = tid & 15, ms = tid >> 4;
            #pragma unroll
            for (int r = 0; r < 4; r++) As[kk][ms + 16*r] = A[(long)(m0 + ms + 16*r) * lda + (k0 + kk)];
        }
        {
            int n = tid & 63, ks = tid >> 6;
            #pragma unroll
            for (int r = 0; r < 4; r++) Bs[ks*4+r][n] = B[(long)(k0 + ks*4 + r) * ldb + (n0 + n)];
        }
        __syncthreads();
        #pragma unroll
        for (int kk = 0; kk < 16; kk++) {
            float a0 = As[kk][row*4+0], a1 = As[kk][row*4+1];
            float a2 = As[kk][row*4+2], a3 = As[kk][row*4+3];
            float b0 = Bs[kk][col*4+0], b1 = Bs[kk][col*4+1];
            float b2 = Bs[kk][col*4+2], b3 = Bs[kk][col*4+3];
            acc[0][0] += a0*b0; acc[0][1] += a0*b1; acc[0][2] += a0*b2; acc[0][3] += a0*b3;
            acc[1][0] += a1*b0; acc[1][1] += a1*b1; acc[1][2] += a1*b2; acc[1][3] += a1*b3;
            acc[2][0] += a2*b0; acc[2][1] += a2*b1; acc[2][2] += a2*b2; acc[2][3] += a2*b3;
            acc[3][0] += a3*b0; acc[3][1] += a3*b1; acc[3][2] += a3*b2; acc[3][3] += a3*b3;
        }
        __syncthreads();
    }
    #pragma unroll
    for (int i = 0; i < 4; i++)
        #pragma unroll
        for (int j = 0; j < 4; j++)
            C[(long)(m0 + row*4 + i) * ldc + n0 + col*4 + j] = __float2bfloat16_rn(acc[i][j]);
}

__device__ __forceinline__ uint32_t smaddr(const void* p) {
    return (uint32_t)__cvta_generic_to_shared(p);
}
__device__ __forceinline__ void cpasync16(uint32_t dst, const void* src) {
    asm volatile("cp.async.cg.shared.global [%0],[%1],16;" :: "r"(dst), "l"(src));
}
__device__ __forceinline__ void ldsm4(uint32_t& r0, uint32_t& r1, uint32_t& r2, uint32_t& r3, uint32_t a) {
    asm volatile("ldmatrix.sync.aligned.m8n8.x4.shared.b16 {%0,%1,%2,%3},[%4];"
                 : "=r"(r0), "=r"(r1), "=r"(r2), "=r"(r3) : "r"(a));
}
__device__ __forceinline__ void ldsm4t(uint32_t& r0, uint32_t& r1, uint32_t& r2, uint32_t& r3, uint32_t a) {
    asm volatile("ldmatrix.sync.aligned.m8n8.x4.trans.shared.b16 {%0,%1,%2,%3},[%4];"
                 : "=r"(r0), "=r"(r1), "=r"(r2), "=r"(r3) : "r"(a));
}
__device__ __forceinline__ void mma16816(float* d, const uint32_t* a, const uint32_t* b) {
    asm volatile("mma.sync.aligned.m16n8k16.row.col.f32.bf16.bf16.f32 "
                 "{%0,%1,%2,%3},{%4,%5,%6,%7},{%8,%9},{%0,%1,%2,%3};"
                 : "+f"(d[0]), "+f"(d[1]), "+f"(d[2]), "+f"(d[3])
                 : "r"(a[0]), "r"(a[1]), "r"(a[2]), "r"(a[3]), "r"(b[0]), "r"(b[1]));
}

// mma.sync GEMM: 128x128x32 tile, 8 warps (2x4), warp tile 64x32.
template<int TA, int TB, int EPI, int OB>
__global__ __launch_bounds__(256)
void mma_gemm(const __nv_bfloat16* __restrict__ A, const __nv_bfloat16* __restrict__ B,
              void* __restrict__ Cv, int K, int lda, int ldb, int ldc,
              long sA, long sB, long sC,
              const float* __restrict__ bias,
              const float* __restrict__ scale,
              const float* __restrict__ Cin, const float* __restrict__ resid,
              const float* __restrict__ gammap, float* __restrict__ partial,
              const float* __restrict__ wcolg, void* __restrict__ C2v)
{
    constexpr int ASZ = TA ? 32*136 : 128*40;
    constexpr int BSZ = TB ? 128*40 : 32*136;
    __shared__ __align__(16) __nv_bfloat16 Ash[3][ASZ];
    __shared__ __align__(16) __nv_bfloat16 Bsh[3][BSZ];
    __shared__ float rsb[(EPI == E_EXP) ? 128 : 1][4];

    int b = blockIdx.z;
    A += (long)b * sA; B += (long)b * sB;
    float* Cf = (float*)Cv + (long)b * sC;
    __nv_bfloat16* Cb = (__nv_bfloat16*)Cv + (long)b * sC;
    __nv_bfloat16* C2b = (EPI == E_STACK) ? (__nv_bfloat16*)C2v + (long)b * OD_ * NN : nullptr;
    const float* CinB   = (EPI == E_FINAL) ? Cin   + (long)b * sC : nullptr;
    const float* residB = (EPI == E_FINAL) ? resid + (long)b * sC : nullptr;
    const float* invB   = (EPI == E_INV)   ? scale + (long)b * NN : nullptr;
    const float* wB     = (EPI == E_EXP)   ? wcolg + (long)b * NN : nullptr;

    int n0 = blockIdx.x * 128, m0 = blockIdx.y * 128;
    int tid = threadIdx.x;
    int wid = tid >> 5, lane = tid & 31;
    int wm = (wid >> 2) * 64, wn = (wid & 3) * 32;
    float acc[4][4][4] = {};
    int KT = K / 32;

    auto issueA = [&](int kt, int buf) {
        int k0 = kt * 32;
        if (TA) {
            #pragma unroll
            for (int it = 0; it < 2; it++) {
                int kr = (tid >> 4) + it * 16, mc = (tid & 15) * 8;
                cpasync16(smaddr(&Ash[buf][kr * 136 + mc]), A + (long)(k0 + kr) * lda + m0 + mc);
            }
        } else {
            #pragma unroll
            for (int it = 0; it < 2; it++) {
                int mr = (tid >> 2) + it * 64, kc = (tid & 3) * 8;
                cpasync16(smaddr(&Ash[buf][mr * 40 + kc]), A + (long)(m0 + mr) * lda + k0 + kc);
            }
        }
    };
    auto issueB = [&](int kt, int buf) {
        int k0 = kt * 32;
        if (TB) {
            #pragma unroll
            for (int it = 0; it < 2; it++) {
                int nr = (tid >> 2) + it * 64, kc = (tid & 3) * 8;
                cpasync16(smaddr(&Bsh[buf][nr * 40 + kc]), B + (long)(n0 + nr) * ldb + k0 + kc);
            }
        } else {
            #pragma unroll
            for (int it = 0; it < 2; it++) {
                int kr = (tid >> 4) + it * 16, nc = (tid & 15) * 8;
                cpasync16(smaddr(&Bsh[buf][kr * 136 + nc]), B + (long)(k0 + kr) * ldb + n0 + nc);
            }
        }
    };

    issueA(0, 0); issueB(0, 0);
    asm volatile("cp.async.commit_group;");
    if (KT > 1) { issueA(1, 1); issueB(1, 1); asm volatile("cp.async.commit_group;"); }

    for (int kt = 0; kt < KT; kt++) {
        if (kt < KT - 1) asm volatile("cp.async.wait_group 1;");
        else             asm volatile("cp.async.wait_group 0;");
        __syncthreads();
        if (kt + 2 < KT) {
            issueA(kt + 2, (kt + 2) % 3);
            issueB(kt + 2, (kt + 2) % 3);
            asm volatile("cp.async.commit_group;");
        }
        int cur = kt % 3;
        #pragma unroll
        for (int ks = 0; ks < 2; ks++) {
            uint32_t af[4][4];
            #pragma unroll
            for (int mf = 0; mf < 4; mf++) {
                if (!TA) {
                    uint32_t a = smaddr(&Ash[cur][(wm + mf*16 + (lane & 15)) * 40 + ks*16 + (lane >> 4) * 8]);
                    ldsm4(af[mf][0], af[mf][1], af[mf][2], af[mf][3], a);
                } else {
                    uint32_t a = smaddr(&Ash[cur][(ks*16 + (lane >> 4) * 8 + (lane & 7)) * 136
                                                  + wm + mf*16 + ((lane >> 3) & 1) * 8]);
                    ldsm4t(af[mf][0], af[mf][1], af[mf][2], af[mf][3], a);
                }
            }
            uint32_t bfr[4][2];
            #pragma unroll
            for (int nf2 = 0; nf2 < 2; nf2++) {
                uint32_t r0, r1, r2, r3;
                if (TB) {
                    uint32_t a = smaddr(&Bsh[cur][(wn + nf2*16 + (lane & 7) + (lane >> 4) * 8) * 40
                                                  + ks*16 + ((lane >> 3) & 1) * 8]);
                    ldsm4(r0, r1, r2, r3, a);
                } else {
                    uint32_t a = smaddr(&Bsh[cur][(ks*16 + ((lane >> 3) & 1) * 8 + (lane & 7)) * 136
                                                  + wn + nf2*16 + (lane >> 4) * 8]);
                    ldsm4t(r0, r1, r2, r3, a);
                }
                bfr[nf2*2][0] = r0; bfr[nf2*2][1] = r1;
                bfr[nf2*2+1][0] = r2; bfr[nf2*2+1][1] = r3;
            }
            #pragma unroll
            for (int mf = 0; mf < 4; mf++)
                #pragma unroll
                for (int nf = 0; nf < 4; nf++)
                    mma16816(acc[mf][nf], af[mf], bfr[nf]);
        }
        __syncthreads();
    }

    if (EPI == E_EXP) {
        float rsum[4][2] = {};
        #pragma unroll
        for (int mf = 0; mf < 4; mf++)
            #pragma unroll
            for (int nf = 0; nf < 4; nf++)
                #pragma unroll
                for (int h = 0; h < 2; h++) {
                    int r = m0 + wm + mf*16 + (lane >> 2) + h*8;
                    int c = n0 + wn + nf*8 + (lane & 3) * 2;
                    float e0 = __expf(fminf(acc[mf][nf][h*2],   50.f)) * wB[c];
                    float e1 = __expf(fminf(acc[mf][nf][h*2+1], 50.f)) * wB[c+1];
                    *(__nv_bfloat162*)(Cb + (long)r * ldc + c) = __floats2bfloat162_rn(e0, e1);
                    rsum[mf][h] += e0 + e1;
                }
        #pragma unroll
        for (int mf = 0; mf < 4; mf++)
            #pragma unroll
            for (int h = 0; h < 2; h++) {
                rsum[mf][h] += __shfl_xor_sync(0xffffffffu, rsum[mf][h], 1);
                rsum[mf][h] += __shfl_xor_sync(0xffffffffu, rsum[mf][h], 2);
                if ((lane & 3) == 0)
                    rsb[wm + mf*16 + (lane >> 2) + h*8][wid & 3] = rsum[mf][h];
            }
        __syncthreads();
        if (tid < 128)
            partial[((long)b*32 + blockIdx.x)*NN + (m0 + tid)] =
                rsb[tid][0] + rsb[tid][1] + rsb[tid][2] + rsb[tid][3];
        return;
    }

    float gam = (EPI == E_FINAL) ? gammap[0] : 0.f;
    #pragma unroll
    for (int mf = 0; mf < 4; mf++) {
        #pragma unroll
        for (int nf = 0; nf < 4; nf++) {
            int rbase = m0 + wm + mf*16 + (lane >> 2);
            int c = n0 + wn + nf*8 + (lane & 3) * 2;
            #pragma unroll
            for (int h = 0; h < 2; h++) {
                int r = rbase + h * 8;
                long off = (long)r * ldc + c;
                float v0 = acc[mf][nf][h*2], v1 = acc[mf][nf][h*2+1];
                if (EPI == E_STACK) {
                    float bv = bias[r]; v0 += bv; v1 += bv;
                    if (r < 128) {      // projection rows: relu -> C (uniform per CTA)
                        v0 = fmaxf(v0, 0.f); v1 = fmaxf(v1, 0.f);
                        *(__nv_bfloat162*)(Cb + off) = __floats2bfloat162_rn(v0, v1);
                    } else {            // value rows -> C2
                        *(__nv_bfloat162*)(C2b + (long)(r - 128) * ldc + c) = __floats2bfloat162_rn(v0, v1);
                    }
                    continue;
                } else if (EPI == E_INV) {
                    v0 *= invB[c]; v1 *= invB[c+1];
                } else if (EPI == E_FINAL) {
                    v0 += CinB[off]; v1 += CinB[off+1];
                    float sc = scale[r], sf = bias[r];
                    v0 = fmaxf(v0 * sc + sf, 0.f);
                    v1 = fmaxf(v1 * sc + sf, 0.f);
                    v0 = residB[off]   + gam * v0;
                    v1 = residB[off+1] + gam * v1;
                }
                if (OB) *(__nv_bfloat162*)(Cb + off) = __floats2bfloat162_rn(v0, v1);
                else    { Cf[off] = v0; Cf[off+1] = v1; }
            }
        }
    }
}

__global__ void inv_kernel(const float* __restrict__ part, float* __restrict__ inv)
{
    int i = blockIdx.x * 256 + threadIdx.x;
    int b = i >> 12, n = i & (NN - 1);
    float s = 0.f;
    #pragma unroll 8
    for (int x = 0; x < 32; x++) s += part[((long)b*32 + x)*NN + n];
    inv[i] = 1.f / s;
}

__global__ void scale_vl_kernel(__nv_bfloat16* __restrict__ vl, const float* __restrict__ inv)
{
    long i = blockIdx.x * 256L + threadIdx.x;
    int n = (int)(i & 2047) * 2;
    long b = i >> 19;
    const float* ib = inv + b * NN;
    __nv_bfloat162 v = ((__nv_bfloat162*)vl)[i];
    float2 f = __bfloat1622float2(v);
    ((__nv_bfloat162*)vl)[i] = __floats2bfloat162_rn(f.x * ib[n], f.y * ib[n+1]);
}

#define SYM(p, T, s) do { void* t_; cudaGetSymbolAddress(&t_, s); p = (T*)t_; } while (0)

extern "C" void kernel_launch(void* const* d_in, const int* in_sizes, int n_in,
                              void* d_out, int out_size)
{
    const float* high   = (const float*)d_in[0];
    const float* lowf   = (const float*)d_in[1];
    const float* W_high = (const float*)d_in[2];
    const float* bn_hs  = (const float*)d_in[3];
    const float* bn_hb  = (const float*)d_in[4];
    const float* bn_hm  = (const float*)d_in[5];
    const float* bn_hv  = (const float*)d_in[6];
    const float* W_low  = (const float*)d_in[7];
    const float* bn_ls  = (const float*)d_in[8];
    const float* bn_lb  = (const float*)d_in[9];
    const float* bn_lm  = (const float*)d_in[10];
    const float* bn_lv  = (const float*)d_in[11];
    const float* W_q    = (const float*)d_in[12];
    const float* b_q    = (const float*)d_in[13];
    const float* W_k    = (const float*)d_in[14];
    const float* b_k    = (const float*)d_in[15];
    const float* W_vh   = (const float*)d_in[16];
    const float* b_vh   = (const float*)d_in[17];
    const float* W_vl   = (const float*)d_in[18];
    const float* b_vl   = (const float*)d_in[19];
    const float* W_out  = (const float*)d_in[20];
    const float* bn_os  = (const float*)d_in[21];
    const float* bn_ob  = (const float*)d_in[22];
    const float* bn_om  = (const float*)d_in[23];
    const float* bn_ov  = (const float*)d_in[24];
    const float* gamma  = (const float*)d_in[25];
    float* out = (float*)d_out;

    __nv_bfloat16 *pHighb, *pLowb, *pHeb, *pLeb, *pKb, *pVhpb, *pVlpb, *pAttnb;
    __nv_bfloat16 *pWsh, *pWsl, *pWm;
    float *pZ, *pPart, *pInv, *pW, *pBsh, *pBsl, *pAo, *pBo;
    SYM(pHighb, __nv_bfloat16, g_highb); SYM(pLowb, __nv_bfloat16, g_lowb);
    SYM(pHeb, __nv_bfloat16, g_heb); SYM(pLeb, __nv_bfloat16, g_leb);
    SYM(pKb, __nv_bfloat16, g_kb);
    SYM(pVhpb, __nv_bfloat16, g_vhpb); SYM(pVlpb, __nv_bfloat16, g_vlpb);
    SYM(pAttnb, __nv_bfloat16, g_attnb);
    SYM(pWsh, __nv_bfloat16, g_Wsh); SYM(pWsl, __nv_bfloat16, g_Wsl); SYM(pWm, __nv_bfloat16, g_Wm);
    SYM(pZ, float, g_z); SYM(pPart, float, g_part); SYM(pInv, float, g_inv); SYM(pW, float, g_w);
    SYM(pBsh, float, g_bsh); SYM(pBsl, float, g_bsl);
    SYM(pAo, float, g_ao); SYM(pBo, float, g_bo);

    // 1) fold: weights, M = WqT*Wk, wv, c, biases
    fold_kernel<<<256, 256>>>(W_high, bn_hs, bn_hb, bn_hm, bn_hv,
                              W_low, bn_ls, bn_lb, bn_lm, bn_lv,
                              bn_os, bn_ob, bn_om, bn_ov,
                              W_out, b_vh, b_vl, W_q, b_q, W_k, b_k);
    // 2) combined value weights -> stacked rows 128-383
    gemm_small<<<dim3(4,4,1), 256>>>(W_out, W_vh, pWsh + 128*HD_, 256, 512, 256, 256);
    gemm_small<<<dim3(8,4,1), 256>>>(W_out + 256, W_vl, pWsl + 128*LD_, 256, 512, 512, 512);
    // 3) inputs -> bf16
    tobf16_kernel<<<(BB*HD_*NN/4 + 255)/256, 256>>>(high, pHighb, (long)BB*HD_*NN/4);
    upsample_kernel<<<(BB*LD_*NN + 255)/256, 256>>>(lowf, pLowb);

    // 4) stacked projections: [he; vh'] over highb, [le; vl'] over lowb
    mma_gemm<0,0,E_STACK,1><<<dim3(32,3,BB), 256>>>(pWsh, pHighb, pHeb,
        HD_, HD_, NN, NN, 0, (long)HD_*NN, (long)128*NN, pBsh,
        nullptr, nullptr, nullptr, nullptr, nullptr, nullptr, pVhpb);
    mma_gemm<0,0,E_STACK,1><<<dim3(32,3,BB), 256>>>(pWsl, pLowb, pLeb,
        LD_, LD_, NN, NN, 0, (long)LD_*NN, (long)128*NN, pBsl,
        nullptr, nullptr, nullptr, nullptr, nullptr, nullptr, pVlpb);

    // 5) w[m] = exp(wv.le_m + c);  kp = M.le
    wcol_kernel<<<BB*NN/256, 256>>>(pLeb, pW);
    mma_gemm<0,0,E_NONE,1><<<dim3(32,1,BB), 256>>>(pWm, pLeb, pKb,
        EE, EE, NN, NN, 0, (long)128*NN, (long)128*NN, nullptr,
        nullptr, nullptr, nullptr, nullptr, nullptr, nullptr, nullptr);

    // 6) energy via he.kp -> E = exp(s)*w[m] + partial row sums
    mma_gemm<1,0,E_EXP,1><<<dim3(32,32,BB), 256>>>(pHeb, pKb, pAttnb,
        EE, NN, NN, NN, (long)128*NN, (long)128*NN, (long)NN*NN, nullptr,
        nullptr, nullptr, nullptr, nullptr, pPart, pW, nullptr);
    inv_kernel<<<BB*NN/256, 256>>>(pPart, pInv);
    scale_vl_kernel<<<(int)((long)BB*OD_*NN/2/256), 256>>>(pVlpb, pInv);

    // 7) z = (vh' @ E^T) * inv[col]
    mma_gemm<0,1,E_INV,0><<<dim3(32,2,BB), 256>>>(pVhpb, pAttnb, pZ,
        NN, NN, NN, NN, (long)OD_*NN, (long)NN*NN, (long)OD_*NN, nullptr,
        pInv, nullptr, nullptr, nullptr, nullptr, nullptr, nullptr);

    // 8) out = high + gamma * relu(ao*(z + vls @ E) + bo)
    mma_gemm<0,0,E_FINAL,0><<<dim3(32,2,BB), 256>>>(pVlpb, pAttnb, out,
        NN, NN, NN, NN, (long)OD_*NN, (long)NN*NN, (long)OD_*NN, pBo,
        pAo, pZ, high, gamma, nullptr, nullptr, nullptr);
}

// round 15
// speedup vs baseline: 1.1146x; 1.0249x over previous
#include <cuda_runtime.h>
#include <cuda_bf16.h>
#include <math.h>
#include <stdint.h>

#define BB 4
#define HD_ 256
#define LD_ 512
#define OD_ 256
#define EE 64
#define NN 4096
#define NLOW 1024
#define EPS_ 1e-5f

__device__ __nv_bfloat16 g_highb[BB*HD_*NN];
__device__ __nv_bfloat16 g_lowb [BB*LD_*NN];
__device__ __nv_bfloat16 g_heb  [BB*128*NN];
__device__ __nv_bfloat16 g_leb  [BB*128*NN];
__device__ __nv_bfloat16 g_kb   [BB*128*NN];
__device__ __nv_bfloat16 g_vhpb [BB*OD_*NN];
__device__ __nv_bfloat16 g_vlpb [BB*OD_*NN];
__device__ __nv_bfloat16 g_zb  [BB*OD_*NN];
__device__ __nv_bfloat16 g_attnb[(size_t)BB*NN*NN];
__device__ float g_part[BB*32*NN];
__device__ float g_inv [BB*NN];
__device__ float g_w   [BB*NN];
__device__ __nv_bfloat16 g_Wsh[384*HD_];
__device__ __nv_bfloat16 g_Wsl[384*LD_];
__device__ __nv_bfloat16 g_Wm [128*EE];
__device__ float g_bsh[384], g_bsl[384];
__device__ float g_wv[EE];
__device__ float g_c;
__device__ float g_ao[OD_], g_bo[OD_];

__global__ void fold_kernel(const float* __restrict__ W_high,
                            const float* __restrict__ sh, const float* __restrict__ bh,
                            const float* __restrict__ mh, const float* __restrict__ vh,
                            const float* __restrict__ W_low,
                            const float* __restrict__ sl, const float* __restrict__ bl,
                            const float* __restrict__ ml, const float* __restrict__ vl,
                            const float* __restrict__ os_, const float* __restrict__ ob,
                            const float* __restrict__ om, const float* __restrict__ ov,
                            const float* __restrict__ W_out,
                            const float* __restrict__ b_vh, const float* __restrict__ b_vl,
                            const float* __restrict__ W_q, const float* __restrict__ b_q,
                            const float* __restrict__ W_k, const float* __restrict__ b_k)
{
    int i = blockIdx.x * blockDim.x + threadIdx.x;
    if (i < 128*HD_) {
        int o = i / HD_;
        g_Wsh[i] = (o < EE) ? __float2bfloat16_rn(W_high[i] * sh[o] * rsqrtf(vh[o] + EPS_))
                            : __nv_bfloat16(0.f);
    }
    if (i < 128*LD_) {
        int o = i / LD_;
        g_Wsl[i] = (o < EE) ? __float2bfloat16_rn(W_low[i] * sl[o] * rsqrtf(vl[o] + EPS_))
                            : __nv_bfloat16(0.f);
    }
    if (i < 128*EE) {
        int e = i >> 6, f = i & 63;
        if (e < EE) {
            float s = 0.f;
            for (int o = 0; o < EE; o++) s += W_q[o*EE + e] * W_k[o*EE + f];
            g_Wm[i] = __float2bfloat16_rn(s);
        } else g_Wm[i] = __nv_bfloat16(0.f);
    }
    if (i < EE) {
        float s = 0.f;
        for (int o = 0; o < EE; o++) s += b_q[o] * W_k[o*EE + i];
        g_wv[i] = s;
        if (i == 0) {
            float c = 0.f;
            for (int o = 0; o < EE; o++) c += b_q[o] * b_k[o];
            g_c = c;
        }
    }
    if (i < 128) {
        if (i < EE) {
            float ah = sh[i] * rsqrtf(vh[i] + EPS_); g_bsh[i] = bh[i] - mh[i] * ah;
            float al = sl[i] * rsqrtf(vl[i] + EPS_); g_bsl[i] = bl[i] - ml[i] * al;
        } else { g_bsh[i] = 0.f; g_bsl[i] = 0.f; }
    }
    if (i < OD_) {
        float a = os_[i] * rsqrtf(ov[i] + EPS_);
        g_ao[i] = a; g_bo[i] = ob[i] - om[i] * a;
    }
    if (i < 2*OD_) {
        int o = (i < OD_) ? i : i - OD_;
        const float* wrow = W_out + (long)o * (2*OD_) + ((i < OD_) ? 0 : OD_);
        const float* bv   = (i < OD_) ? b_vh : b_vl;
        float s = 0.f;
        for (int j = 0; j < OD_; j++) s += wrow[j] * bv[j];
        if (i < OD_) g_bsh[128 + o] = s; else g_bsl[128 + o] = s;
    }
}

__global__ void tobf16_kernel(const float* __restrict__ in, __nv_bfloat16* __restrict__ out, long n4)
{
    long i = blockIdx.x * (long)blockDim.x + threadIdx.x;
    if (i >= n4) return;
    float4 v = ((const float4*)in)[i];
    __nv_bfloat162* o = (__nv_bfloat162*)(out + i * 4);
    o[0] = __floats2bfloat162_rn(v.x, v.y);
    o[1] = __floats2bfloat162_rn(v.z, v.w);
}

__global__ void upsample_kernel(const float* __restrict__ low, __nv_bfloat16* __restrict__ out)
{
    int idx = blockIdx.x * blockDim.x + threadIdx.x;
    if (idx >= BB*LD_*NN) return;
    int x = idx & 63, y = (idx >> 6) & 63;
    int bc = idx >> 12;
    float fy = y * 0.5f - 0.25f, fx = x * 0.5f - 0.25f;
    int y0 = (int)floorf(fy); float wy = fy - (float)y0;
    int x0 = (int)floorf(fx); float wx = fx - (float)x0;
    int y1 = min(y0 + 1, 31); y0 = max(y0, 0);
    int x1 = min(x0 + 1, 31); x0 = max(x0, 0);
    const float* src = low + (long)bc * NLOW;
    float v00 = src[y0*32+x0], v01 = src[y0*32+x1];
    float v10 = src[y1*32+x0], v11 = src[y1*32+x1];
    out[idx] = __float2bfloat16_rn((1.f-wy)*((1.f-wx)*v00 + wx*v01) + wy*((1.f-wx)*v10 + wx*v11));
}

__global__ void wcol_kernel(const __nv_bfloat16* __restrict__ le, float* __restrict__ w)
{
    int i = blockIdx.x * 256 + threadIdx.x;
    int b = i >> 12, m = i & (NN - 1);
    const __nv_bfloat16* lb = le + (long)b * 128 * NN + m;
    float s = g_c;
    #pragma unroll 8
    for (int f = 0; f < EE; f++) s += g_wv[f] * __bfloat162float(lb[(long)f * NN]);
    w[i] = __expf(s);
}

enum { E_NONE = 0, E_STACK = 1, E_EXP = 4, E_INV = 5, E_FINAL = 6 };

__global__ __launch_bounds__(256)
void gemm_small(const float* __restrict__ A, const float* __restrict__ B,
                __nv_bfloat16* __restrict__ C, int K, int lda, int ldb, int ldc)
{
    __shared__ float As[16][68];
    __shared__ float Bs[16][68];
    int m0 = blockIdx.y * 64, n0 = blockIdx.x * 64;
    int tid = threadIdx.x;
    int row = tid >> 4, col = tid & 15;
    float acc[4][4] = {};
    for (int k0 = 0; k0 < K; k0 += 16) {
        {
            int kk = tid & 15, ms = tid >> 4;
            #pragma unroll
            for (int r = 0; r < 4; r++) As[kk][ms + 16*r] = A[(long)(m0 + ms + 16*r) * lda + (k0 + kk)];
        }
        {
            int n = tid & 63, ks = tid >> 6;
            #pragma unroll
            for (int r = 0; r < 4; r++) Bs[ks*4+r][n] = B[(long)(k0 + ks*4 + r) * ldb + (n0 + n)];
        }
        __syncthreads();
        #pragma unroll
        for (int kk = 0; kk < 16; kk++) {
            float a0 = As[kk][row*4+0], a1 = As[kk][row*4+1];
            float a2 = As[kk][row*4+2], a3 = As[kk][row*4+3];
            float b0 = Bs[kk][col*4+0], b1 = Bs[kk][col*4+1];
            float b2 = Bs[kk][col*4+2], b3 = Bs[kk][col*4+3];
            acc[0][0] += a0*b0; acc[0][1] += a0*b1; acc[0][2] += a0*b2; acc[0][3] += a0*b3;
            acc[1][0] += a1*b0; acc[1][1] += a1*b1; acc[1][2] += a1*b2; acc[1][3] += a1*b3;
            acc[2][0] += a2*b0; acc[2][1] += a2*b1; acc[2][2] += a2*b2; acc[2][3] += a2*b3;
            acc[3][0] += a3*b0; acc[3][1] += a3*b1; acc[3][2] += a3*b2; acc[3][3] += a3*b3;
        }
        __syncthreads();
    }
    #pragma unroll
    for (int i = 0; i < 4; i++)
        #pragma unroll
        for (int j = 0; j < 4; j++)
            C[(long)(m0 + row*4 + i) * ldc + n0 + col*4 + j] = __float2bfloat16_rn(acc[i][j]);
}

__device__ __forceinline__ uint32_t smaddr(const void* p) {
    return (uint32_t)__cvta_generic_to_shared(p);
}
__device__ __forceinline__ void cpasync16(uint32_t dst, const void* src) {
    asm volatile("cp.async.cg.shared.global [%0],[%1],16;" :: "r"(dst), "l"(src));
}
__device__ __forceinline__ void ldsm4(uint32_t& r0, uint32_t& r1, uint32_t& r2, uint32_t& r3, uint32_t a) {
    asm volatile("ldmatrix.sync.aligned.m8n8.x4.shared.b16 {%0,%1,%2,%3},[%4];"
                 : "=r"(r0), "=r"(r1), "=r"(r2), "=r"(r3) : "r"(a));
}
__device__ __forceinline__ void ldsm4t(uint32_t& r0, uint32_t& r1, uint32_t& r2, uint32_t& r3, uint32_t a) {
    asm volatile("ldmatrix.sync.aligned.m8n8.x4.trans.shared.b16 {%0,%1,%2,%3},[%4];"
                 : "=r"(r0), "=r"(r1), "=r"(r2), "=r"(r3) : "r"(a));
}
__device__ __forceinline__ void mma16816(float* d, const uint32_t* a, const uint32_t* b) {
    asm volatile("mma.sync.aligned.m16n8k16.row.col.f32.bf16.bf16.f32 "
                 "{%0,%1,%2,%3},{%4,%5,%6,%7},{%8,%9},{%0,%1,%2,%3};"
                 : "+f"(d[0]), "+f"(d[1]), "+f"(d[2]), "+f"(d[3])
                 : "r"(a[0]), "r"(a[1]), "r"(a[2]), "r"(a[3]), "r"(b[0]), "r"(b[1]));
}

// mma.sync GEMM: 128x128x32 tile, 8 warps (2x4), warp tile 64x32. MB = min blocks/SM.
template<int TA, int TB, int EPI, int OB, int MB>
__global__ __launch_bounds__(256, MB)
void mma_gemm(const __nv_bfloat16* __restrict__ A, const __nv_bfloat16* __restrict__ B,
              void* __restrict__ Cv, int K, int lda, int ldb, int ldc,
              long sA, long sB, long sC,
              const float* __restrict__ bias,
              const float* __restrict__ scale,
              const void* __restrict__ Cin, const float* __restrict__ resid,
              const float* __restrict__ gammap, float* __restrict__ partial,
              const float* __restrict__ wcolg, void* __restrict__ C2v)
{
    constexpr int ASZ = TA ? 32*136 : 128*40;
    constexpr int BSZ = TB ? 128*40 : 32*136;
    __shared__ __align__(16) __nv_bfloat16 Ash[3][ASZ];
    __shared__ __align__(16) __nv_bfloat16 Bsh[3][BSZ];
    __shared__ float rsb[(EPI == E_EXP) ? 128 : 1][4];

    int b = blockIdx.z;
    A += (long)b * sA; B += (long)b * sB;
    float* Cf = (float*)Cv + (long)b * sC;
    __nv_bfloat16* Cb = (__nv_bfloat16*)Cv + (long)b * sC;
    __nv_bfloat16* C2b = (EPI == E_STACK) ? (__nv_bfloat16*)C2v + (long)b * OD_ * NN : nullptr;
    const __nv_bfloat16* CinB = (EPI == E_FINAL) ? (const __nv_bfloat16*)Cin + (long)b * sC : nullptr;
    const float* residB = (EPI == E_FINAL) ? resid + (long)b * sC : nullptr;
    const float* invB   = (EPI == E_INV)   ? scale + (long)b * NN : nullptr;
    const float* wB     = (EPI == E_EXP)   ? wcolg + (long)b * NN : nullptr;

    int n0 = blockIdx.x * 128, m0 = blockIdx.y * 128;
    int tid = threadIdx.x;
    int wid = tid >> 5, lane = tid & 31;
    int wm = (wid >> 2) * 64, wn = (wid & 3) * 32;
    float acc[4][4][4] = {};
    int KT = K / 32;

    auto issueA = [&](int kt, int buf) {
        int k0 = kt * 32;
        if (TA) {
            #pragma unroll
            for (int it = 0; it < 2; it++) {
                int kr = (tid >> 4) + it * 16, mc = (tid & 15) * 8;
                cpasync16(smaddr(&Ash[buf][kr * 136 + mc]), A + (long)(k0 + kr) * lda + m0 + mc);
            }
        } else {
            #pragma unroll
            for (int it = 0; it < 2; it++) {
                int mr = (tid >> 2) + it * 64, kc = (tid & 3) * 8;
                cpasync16(smaddr(&Ash[buf][mr * 40 + kc]), A + (long)(m0 + mr) * lda + k0 + kc);
            }
        }
    };
    auto issueB = [&](int kt, int buf) {
        int k0 = kt * 32;
        if (TB) {
            #pragma unroll
            for (int it = 0; it < 2; it++) {
                int nr = (tid >> 2) + it * 64, kc = (tid & 3) * 8;
                cpasync16(smaddr(&Bsh[buf][nr * 40 + kc]), B + (long)(n0 + nr) * ldb + k0 + kc);
            }
        } else {
            #pragma unroll
            for (int it = 0; it < 2; it++) {
                int kr = (tid >> 4) + it * 16, nc = (tid & 15) * 8;
                cpasync16(smaddr(&Bsh[buf][kr * 136 + nc]), B + (long)(k0 + kr) * ldb + n0 + nc);
            }
        }
    };

    issueA(0, 0); issueB(0, 0);
    asm volatile("cp.async.commit_group;");
    if (KT > 1) { issueA(1, 1); issueB(1, 1); asm volatile("cp.async.commit_group;"); }

    for (int kt = 0; kt < KT; kt++) {
        if (kt < KT - 1) asm volatile("cp.async.wait_group 1;");
        else             asm volatile("cp.async.wait_group 0;");
        __syncthreads();
        if (kt + 2 < KT) {
            issueA(kt + 2, (kt + 2) % 3);
            issueB(kt + 2, (kt + 2) % 3);
            asm volatile("cp.async.commit_group;");
        }
        int cur = kt % 3;
        #pragma unroll
        for (int ks = 0; ks < 2; ks++) {
            uint32_t af[4][4];
            #pragma unroll
            for (int mf = 0; mf < 4; mf++) {
                if (!TA) {
                    uint32_t a = smaddr(&Ash[cur][(wm + mf*16 + (lane & 15)) * 40 + ks*16 + (lane >> 4) * 8]);
                    ldsm4(af[mf][0], af[mf][1], af[mf][2], af[mf][3], a);
                } else {
                    uint32_t a = smaddr(&Ash[cur][(ks*16 + (lane >> 4) * 8 + (lane & 7)) * 136
                                                  + wm + mf*16 + ((lane >> 3) & 1) * 8]);
                    ldsm4t(af[mf][0], af[mf][1], af[mf][2], af[mf][3], a);
                }
            }
            uint32_t bfr[4][2];
            #pragma unroll
            for (int nf2 = 0; nf2 < 2; nf2++) {
                uint32_t r0, r1, r2, r3;
                if (TB) {
                    uint32_t a = smaddr(&Bsh[cur][(wn + nf2*16 + (lane & 7) + (lane >> 4) * 8) * 40
                                                  + ks*16 + ((lane >> 3) & 1) * 8]);
                    ldsm4(r0, r1, r2, r3, a);
                } else {
                    uint32_t a = smaddr(&Bsh[cur][(ks*16 + ((lane >> 3) & 1) * 8 + (lane & 7)) * 136
                                                  + wn + nf2*16 + (lane >> 4) * 8]);
                    ldsm4t(r0, r1, r2, r3, a);
                }
                bfr[nf2*2][0] = r0; bfr[nf2*2][1] = r1;
                bfr[nf2*2+1][0] = r2; bfr[nf2*2+1][1] = r3;
            }
            #pragma unroll
            for (int mf = 0; mf < 4; mf++)
                #pragma unroll
                for (int nf = 0; nf < 4; nf++)
                    mma16816(acc[mf][nf], af[mf], bfr[nf]);
        }
        __syncthreads();
    }

    if (EPI == E_EXP) {
        float rsum[4][2] = {};
        #pragma unroll
        for (int mf = 0; mf < 4; mf++)
            #pragma unroll
            for (int nf = 0; nf < 4; nf++)
                #pragma unroll
                for (int h = 0; h < 2; h++) {
                    int r = m0 + wm + mf*16 + (lane >> 2) + h*8;
                    int c = n0 + wn + nf*8 + (lane & 3) * 2;
                    float e0 = __expf(fminf(acc[mf][nf][h*2],   50.f)) * wB[c];
                    float e1 = __expf(fminf(acc[mf][nf][h*2+1], 50.f)) * wB[c+1];
                    *(__nv_bfloat162*)(Cb + (long)r * ldc + c) = __floats2bfloat162_rn(e0, e1);
                    rsum[mf][h] += e0 + e1;
                }
        #pragma unroll
        for (int mf = 0; mf < 4; mf++)
            #pragma unroll
            for (int h = 0; h < 2; h++) {
                rsum[mf][h] += __shfl_xor_sync(0xffffffffu, rsum[mf][h], 1);
                rsum[mf][h] += __shfl_xor_sync(0xffffffffu, rsum[mf][h], 2);
                if ((lane & 3) == 0)
                    rsb[wm + mf*16 + (lane >> 2) + h*8][wid & 3] = rsum[mf][h];
            }
        __syncthreads();
        if (tid < 128)
            partial[((long)b*32 + blockIdx.x)*NN + (m0 + tid)] =
                rsb[tid][0] + rsb[tid][1] + rsb[tid][2] + rsb[tid][3];
        return;
    }

    float gam = (EPI == E_FINAL) ? gammap[0] : 0.f;
    #pragma unroll
    for (int mf = 0; mf < 4; mf++) {
        #pragma unroll
        for (int nf = 0; nf < 4; nf++) {
            int rbase = m0 + wm + mf*16 + (lane >> 2);
            int c = n0 + wn + nf*8 + (lane & 3) * 2;
            #pragma unroll
            for (int h = 0; h < 2; h++) {
                int r = rbase + h * 8;
                long off = (long)r * ldc + c;
                float v0 = acc[mf][nf][h*2], v1 = acc[mf][nf][h*2+1];
                if (EPI == E_STACK) {
                    float bv = bias[r]; v0 += bv; v1 += bv;
                    if (r < 128) {
                        v0 = fmaxf(v0, 0.f); v1 = fmaxf(v1, 0.f);
                        *(__nv_bfloat162*)(Cb + off) = __floats2bfloat162_rn(v0, v1);
                    } else {
                        *(__nv_bfloat162*)(C2b + (long)(r - 128) * ldc + c) = __floats2bfloat162_rn(v0, v1);
                    }
                    continue;
                } else if (EPI == E_INV) {
                    v0 *= invB[c]; v1 *= invB[c+1];
                } else if (EPI == E_FINAL) {
                    float2 ci = __bfloat1622float2(*(const __nv_bfloat162*)(CinB + off));
                    v0 += ci.x; v1 += ci.y;
                    float sc = scale[r], sf = bias[r];
                    v0 = fmaxf(v0 * sc + sf, 0.f);
                    v1 = fmaxf(v1 * sc + sf, 0.f);
                    v0 = residB[off]   + gam * v0;
                    v1 = residB[off+1] + gam * v1;
                }
                if (OB) *(__nv_bfloat162*)(Cb + off) = __floats2bfloat162_rn(v0, v1);
                else    { Cf[off] = v0; Cf[off+1] = v1; }
            }
        }
    }
}

__global__ void inv_kernel(const float* __restrict__ part, float* __restrict__ inv)
{
    int i = blockIdx.x * 256 + threadIdx.x;
    int b = i >> 12, n = i & (NN - 1);
    float s = 0.f;
    #pragma unroll 8
    for (int x = 0; x < 32; x++) s += part[((long)b*32 + x)*NN + n];
    inv[i] = 1.f / s;
}

__global__ void scale_vl_kernel(__nv_bfloat16* __restrict__ vl, const float* __restrict__ inv)
{
    long i = blockIdx.x * 256L + threadIdx.x;
    int n = (int)(i & 2047) * 2;
    long b = i >> 19;
    const float* ib = inv + b * NN;
    __nv_bfloat162 v = ((__nv_bfloat162*)vl)[i];
    float2 f = __bfloat1622float2(v);
    ((__nv_bfloat162*)vl)[i] = __floats2bfloat162_rn(f.x * ib[n], f.y * ib[n+1]);
}

#define SYM(p, T, s) do { void* t_; cudaGetSymbolAddress(&t_, s); p = (T*)t_; } while (0)

extern "C" void kernel_launch(void* const* d_in, const int* in_sizes, int n_in,
                              void* d_out, int out_size)
{
    const float* high   = (const float*)d_in[0];
    const float* lowf   = (const float*)d_in[1];
    const float* W_high = (const float*)d_in[2];
    const float* bn_hs  = (const float*)d_in[3];
    const float* bn_hb  = (const float*)d_in[4];
    const float* bn_hm  = (const float*)d_in[5];
    const float* bn_hv  = (const float*)d_in[6];
    const float* W_low  = (const float*)d_in[7];
    const float* bn_ls  = (const float*)d_in[8];
    const float* bn_lb  = (const float*)d_in[9];
    const float* bn_lm  = (const float*)d_in[10];
    const float* bn_lv  = (const float*)d_in[11];
    const float* W_q    = (const float*)d_in[12];
    const float* b_q    = (const float*)d_in[13];
    const float* W_k    = (const float*)d_in[14];
    const float* b_k    = (const float*)d_in[15];
    const float* W_vh   = (const float*)d_in[16];
    const float* b_vh   = (const float*)d_in[17];
    const float* W_vl   = (const float*)d_in[18];
    const float* b_vl   = (const float*)d_in[19];
    const float* W_out  = (const float*)d_in[20];
    const float* bn_os  = (const float*)d_in[21];
    const float* bn_ob  = (const float*)d_in[22];
    const float* bn_om  = (const float*)d_in[23];
    const float* bn_ov  = (const float*)d_in[24];
    const float* gamma  = (const float*)d_in[25];
    float* out = (float*)d_out;

    __nv_bfloat16 *pHighb, *pLowb, *pHeb, *pLeb, *pKb, *pVhpb, *pVlpb, *pAttnb, *pZb;
    __nv_bfloat16 *pWsh, *pWsl, *pWm;
    float *pPart, *pInv, *pW, *pBsh, *pBsl, *pAo, *pBo;
    SYM(pHighb, __nv_bfloat16, g_highb); SYM(pLowb, __nv_bfloat16, g_lowb);
    SYM(pHeb, __nv_bfloat16, g_heb); SYM(pLeb, __nv_bfloat16, g_leb);
    SYM(pKb, __nv_bfloat16, g_kb);
    SYM(pVhpb, __nv_bfloat16, g_vhpb); SYM(pVlpb, __nv_bfloat16, g_vlpb);
    SYM(pAttnb, __nv_bfloat16, g_attnb); SYM(pZb, __nv_bfloat16, g_zb);
    SYM(pWsh, __nv_bfloat16, g_Wsh); SYM(pWsl, __nv_bfloat16, g_Wsl); SYM(pWm, __nv_bfloat16, g_Wm);
    SYM(pPart, float, g_part); SYM(pInv, float, g_inv); SYM(pW, float, g_w);
    SYM(pBsh, float, g_bsh); SYM(pBsl, float, g_bsl);
    SYM(pAo, float, g_ao); SYM(pBo, float, g_bo);

    fold_kernel<<<256, 256>>>(W_high, bn_hs, bn_hb, bn_hm, bn_hv,
                              W_low, bn_ls, bn_lb, bn_lm, bn_lv,
                              bn_os, bn_ob, bn_om, bn_ov,
                              W_out, b_vh, b_vl, W_q, b_q, W_k, b_k);
    gemm_small<<<dim3(4,4,1), 256>>>(W_out, W_vh, pWsh + 128*HD_, 256, 512, 256, 256);
    gemm_small<<<dim3(8,4,1), 256>>>(W_out + 256, W_vl, pWsl + 128*LD_, 256, 512, 512, 512);
    tobf16_kernel<<<(BB*HD_*NN/4 + 255)/256, 256>>>(high, pHighb, (long)BB*HD_*NN/4);
    upsample_kernel<<<(BB*LD_*NN + 255)/256, 256>>>(lowf, pLowb);

    // stacked projections: [he; vh'] over highb, [le; vl'] over lowb
    mma_gemm<0,0,E_STACK,1,2><<<dim3(32,3,BB), 256>>>(pWsh, pHighb, pHeb,
        HD_, HD_, NN, NN, 0, (long)HD_*NN, (long)128*NN, pBsh,
        nullptr, nullptr, nullptr, nullptr, nullptr, nullptr, pVhpb);
    mma_gemm<0,0,E_STACK,1,2><<<dim3(32,3,BB), 256>>>(pWsl, pLowb, pLeb,
        LD_, LD_, NN, NN, 0, (long)LD_*NN, (long)128*NN, pBsl,
        nullptr, nullptr, nullptr, nullptr, nullptr, nullptr, pVlpb);

    // w[m] = exp(wv.le_m + c);  kp = M.le
    wcol_kernel<<<BB*NN/256, 256>>>(pLeb, pW);
    mma_gemm<0,0,E_NONE,1,2><<<dim3(32,1,BB), 256>>>(pWm, pLeb, pKb,
        EE, EE, NN, NN, 0, (long)128*NN, (long)128*NN, nullptr,
        nullptr, nullptr, nullptr, nullptr, nullptr, nullptr, nullptr);

    // energy -> E = exp(s)*w[m] + partial row sums
    mma_gemm<1,0,E_EXP,1,2><<<dim3(32,32,BB), 256>>>(pHeb, pKb, pAttnb,
        EE, NN, NN, NN, (long)128*NN, (long)128*NN, (long)NN*NN, nullptr,
        nullptr, nullptr, nullptr, nullptr, pPart, pW, nullptr);
    inv_kernel<<<BB*NN/256, 256>>>(pPart, pInv);
    scale_vl_kernel<<<(int)((long)BB*OD_*NN/2/256), 256>>>(pVlpb, pInv);

    // z = (vh' @ E^T) * inv[col]   (bf16 out)
    mma_gemm<0,1,E_INV,1,2><<<dim3(32,2,BB), 256>>>(pVhpb, pAttnb, pZb,
        NN, NN, NN, NN, (long)OD_*NN, (long)NN*NN, (long)OD_*NN, nullptr,
        pInv, nullptr, nullptr, nullptr, nullptr, nullptr, nullptr);

    // out = high + gamma * relu(ao*(z + vls @ E) + bo)
    mma_gemm<0,0,E_FINAL,0,2><<<dim3(32,2,BB), 256>>>(pVlpb, pAttnb, out,
        NN, NN, NN, NN, (long)OD_*NN, (long)NN*NN, (long)OD_*NN, pBo,
        pAo, pZb, high, gamma, nullptr, nullptr, nullptr);
}